// round 10
// baseline (speedup 1.0000x reference)
#include <cuda_runtime.h>
#include <math.h>
#include <stdint.h>

// ------------------------------------------------------------------
// Problem constants: B=8, M=1024, C=768
// ------------------------------------------------------------------
#define BATCH 8
#define SEQ   1024
#define CH    768

// Scratch (device globals; allocation-free per harness rules)
__device__ __align__(16) float g_qkv   [BATCH * SEQ * (3 * CH)];
__device__ __align__(16) float g_scores[BATCH * SEQ * SEQ];   // exp'd scores (tf32-rounded)
__device__ __align__(16) float g_lo    [BATCH * SEQ * CH];
__device__ __align__(16) float g_cq    [BATCH * SEQ * CH];
__device__ __align__(16) float g_kv    [BATCH * SEQ * (2 * CH)];
__device__ __align__(16) float g_merge [BATCH * SEQ * CH];
__device__ __align__(16) float g_psum  [8 * BATCH * SEQ];
__device__ __align__(16) float g_rinv  [BATCH * SEQ];
// tf32-pre-rounded copies of harness inputs
__device__ __align__(16) float g_lxr   [BATCH * SEQ * CH];
__device__ __align__(16) float g_txr   [BATCH * SEQ * CH];
__device__ __align__(16) float g_wqkvr [CH * 3 * CH];
__device__ __align__(16) float g_wqr   [CH * CH];
__device__ __align__(16) float g_wkvr  [CH * 2 * CH];
__device__ __align__(16) float g_wffnr [CH * CH];

#define BM 128
#define BN 128
#define BK 16
#define BNP (BN + 8)

// ------------------------------------------------------------------
// TF32 helpers
// ------------------------------------------------------------------
__device__ __forceinline__ unsigned f2tf32(float x) {
    unsigned u;
    asm("cvt.rna.tf32.f32 %0, %1;" : "=r"(u) : "f"(x));
    return u;
}
__device__ __forceinline__ float rnd_tf32(float x) {
    return __uint_as_float(f2tf32(x));
}

__device__ __forceinline__ void mma_tf32(float* d, const unsigned* a, const unsigned* b) {
    asm volatile(
        "mma.sync.aligned.m16n8k8.row.col.f32.tf32.tf32.f32 "
        "{%0,%1,%2,%3}, {%4,%5,%6,%7}, {%8,%9}, {%0,%1,%2,%3};\n"
        : "+f"(d[0]), "+f"(d[1]), "+f"(d[2]), "+f"(d[3])
        : "r"(a[0]), "r"(a[1]), "r"(a[2]), "r"(a[3]),
          "r"(b[0]), "r"(b[1]));
}

// Swizzled k-major tile storage (RAW bits — inputs pre-rounded):
// flat [row*16 + pos], pos(k,row) = (((k&3)+(row>>1))&3)*4 + (k>>2)
__device__ __forceinline__ void store_tile_raw(unsigned* S, int row, int q, float4 v) {
    const int h = (row >> 1) & 3;
    unsigned* base = S + row * 16 + q;
    base[(((0 + h) & 3) << 2)] = __float_as_uint(v.x);
    base[(((1 + h) & 3) << 2)] = __float_as_uint(v.y);
    base[(((2 + h) & 3) << 2)] = __float_as_uint(v.z);
    base[(((3 + h) & 3) << 2)] = __float_as_uint(v.w);
}

__device__ __forceinline__ uint4 ld_frag_swz(const unsigned* S, int row, int c) {
    const int g = (c + (row >> 1)) & 3;
    return *(const uint4*)(S + row * 16 + (g << 2));
}

// ------------------------------------------------------------------
// Elementwise tf32 rounding
// ------------------------------------------------------------------
__global__ void __launch_bounds__(256) round_tf32(
    const float* __restrict__ in, float* __restrict__ out, int n4)
{
    const int i = blockIdx.x * 256 + threadIdx.x;
    if (i < n4) {
        float4 v = ((const float4*)in)[i];
        v.x = rnd_tf32(v.x); v.y = rnd_tf32(v.y);
        v.z = rnd_tf32(v.z); v.w = rnd_tf32(v.w);
        ((float4*)out)[i] = v;
    }
}

// ------------------------------------------------------------------
// NN (BM=128): C[m,n] = sum_k A[m,k]*B[k,n]; batched via blockIdx.z.
// Inputs tf32-pre-rounded; staging stores raw bits.
// EPI = 0: + bias[n];  EPI = 1: * rowinv[row]
// ROUND: epilogue writes tf32-rounded values
// ------------------------------------------------------------------
template<int EPI, bool ROUND>
__global__ void __launch_bounds__(256, 2) mma_nn(
    const float* __restrict__ A, int lda, long long strideA,
    const float* __restrict__ B, int ldb, long long strideB,
    const float* __restrict__ bias,
    const float* __restrict__ rowinv,
    float* __restrict__ C, int ldc, long long strideC,
    int K)
{
    __shared__ unsigned As[2][BM * BK];
    __shared__ unsigned Bs[2][BK][BNP];

    const int b = blockIdx.z;
    A += (size_t)b * strideA;
    B += (size_t)b * strideB;
    C += (size_t)b * strideC;

    const int tid  = threadIdx.x;
    const int lane = tid & 31;
    const int wid  = tid >> 5;
    const int wm = wid & 3;
    const int wn = wid >> 2;
    const int m0 = blockIdx.y * BM;
    const int n0 = blockIdx.x * BN;
    const int c  = lane & 3;
    const int g4 = lane >> 2;

    const int ar = tid >> 2, aq = tid & 3;
    const int bk = tid >> 5, bn4 = (tid & 31) << 2;

    const float* Ap = A + (size_t)(m0 + ar) * lda + 4 * aq;
    const float* Bp = B + (size_t)bk * ldb + n0 + bn4;

    float acc[2][8][4];
    #pragma unroll
    for (int i = 0; i < 2; i++)
        #pragma unroll
        for (int j = 0; j < 8; j++)
            #pragma unroll
            for (int q = 0; q < 4; q++) acc[i][j][q] = 0.f;

    {
        float4 a0 = *(const float4*)Ap;
        float4 a1 = *(const float4*)(Ap + (size_t)64 * lda);
        float4 b0 = *(const float4*)Bp;
        float4 b1 = *(const float4*)(Bp + (size_t)8 * ldb);
        store_tile_raw(As[0], ar,      aq, a0);
        store_tile_raw(As[0], ar + 64, aq, a1);
        *(float4*)&Bs[0][bk][bn4]     = b0;
        *(float4*)&Bs[0][bk + 8][bn4] = b1;
    }
    __syncthreads();

    const int niter = K / BK;
    int buf = 0;
    float4 pa0, pa1, pb0, pb1;

    for (int kt = 0; kt < niter; kt++) {
        const bool has_next = (kt + 1 < niter);
        if (has_next) {
            const float* An = Ap + (kt + 1) * BK;
            pa0 = *(const float4*)An;
            pa1 = *(const float4*)(An + (size_t)64 * lda);
            const float* Bn = Bp + (size_t)(kt + 1) * BK * ldb;
            pb0 = *(const float4*)Bn;
            pb1 = *(const float4*)(Bn + (size_t)8 * ldb);
        }

        const unsigned* Ab = As[buf];

        unsigned af[2][2][4];
        #pragma unroll
        for (int mt = 0; mt < 2; mt++) {
            const int r = wm * 32 + mt * 16 + g4;
            uint4 lo = ld_frag_swz(Ab, r,     c);
            uint4 hi = ld_frag_swz(Ab, r + 8, c);
            af[mt][0][0] = lo.x; af[mt][0][1] = hi.x;
            af[mt][0][2] = lo.y; af[mt][0][3] = hi.y;
            af[mt][1][0] = lo.z; af[mt][1][1] = hi.z;
            af[mt][1][2] = lo.w; af[mt][1][3] = hi.w;
        }

        #pragma unroll
        for (int nt = 0; nt < 8; nt++) {
            const int col = wn * 64 + nt * 8 + g4;
            unsigned b0[2] = { Bs[buf][c][col],     Bs[buf][c + 4][col]  };
            unsigned b1[2] = { Bs[buf][c + 8][col], Bs[buf][c + 12][col] };
            #pragma unroll
            for (int mt = 0; mt < 2; mt++) {
                mma_tf32(acc[mt][nt], af[mt][0], b0);
                mma_tf32(acc[mt][nt], af[mt][1], b1);
            }
        }

        if (has_next) {
            unsigned* An = As[buf ^ 1];
            store_tile_raw(An, ar,      aq, pa0);
            store_tile_raw(An, ar + 64, aq, pa1);
            *(float4*)&Bs[buf ^ 1][bk][bn4]     = pb0;
            *(float4*)&Bs[buf ^ 1][bk + 8][bn4] = pb1;
        }
        __syncthreads();
        buf ^= 1;
    }

    #pragma unroll
    for (int mt = 0; mt < 2; mt++) {
        const int r0 = m0 + wm * 32 + mt * 16 + g4;
        float il0 = 1.f, il1 = 1.f;
        if (EPI == 1) {
            il0 = rowinv[(size_t)b * SEQ + r0];
            il1 = rowinv[(size_t)b * SEQ + r0 + 8];
        }
        #pragma unroll
        for (int nt = 0; nt < 8; nt++) {
            const int col = n0 + wn * 64 + nt * 8 + 2 * c;
            float2 v0, v1;
            if (EPI == 0) {
                float bx = 0.f, by = 0.f;
                if (bias) { bx = bias[col]; by = bias[col + 1]; }
                v0 = make_float2(acc[mt][nt][0] + bx, acc[mt][nt][1] + by);
                v1 = make_float2(acc[mt][nt][2] + bx, acc[mt][nt][3] + by);
            } else {
                v0 = make_float2(acc[mt][nt][0] * il0, acc[mt][nt][1] * il0);
                v1 = make_float2(acc[mt][nt][2] * il1, acc[mt][nt][3] * il1);
            }
            if (ROUND) {
                v0.x = rnd_tf32(v0.x); v0.y = rnd_tf32(v0.y);
                v1.x = rnd_tf32(v1.x); v1.y = rnd_tf32(v1.y);
            }
            *(float2*)(C + (size_t)r0 * ldc + col) = v0;
            *(float2*)(C + (size_t)(r0 + 8) * ldc + col) = v1;
        }
    }
}

// ------------------------------------------------------------------
// NN (BM=64): same structure, half-height CTA for finer wave
// granularity on low-CTA-count GEMMs (PV, cq, ffn).
// Warp grid 2x4 (wm 0..1 over 32-row halves, wn 0..3 over 32-col).
// ------------------------------------------------------------------
template<int EPI, bool ROUND>
__global__ void __launch_bounds__(256, 2) mma_nn64(
    const float* __restrict__ A, int lda, long long strideA,
    const float* __restrict__ B, int ldb, long long strideB,
    const float* __restrict__ bias,
    const float* __restrict__ rowinv,
    float* __restrict__ C, int ldc, long long strideC,
    int K)
{
    __shared__ unsigned As[2][64 * BK];
    __shared__ unsigned Bs[2][BK][BNP];

    const int b = blockIdx.z;
    A += (size_t)b * strideA;
    B += (size_t)b * strideB;
    C += (size_t)b * strideC;

    const int tid  = threadIdx.x;
    const int lane = tid & 31;
    const int wid  = tid >> 5;
    const int wm = wid >> 2;              // 0..1 (32-row half)
    const int wn = wid & 3;               // 0..3 (32-col quarter)
    const int m0 = blockIdx.y * 64;
    const int n0 = blockIdx.x * BN;
    const int c  = lane & 3;
    const int g4 = lane >> 2;

    const int ar = tid >> 2, aq = tid & 3;          // 64 rows x 4 quads
    const int bk = tid >> 5, bn4 = (tid & 31) << 2;

    const float* Ap = A + (size_t)(m0 + ar) * lda + 4 * aq;
    const float* Bp = B + (size_t)bk * ldb + n0 + bn4;

    float acc[2][4][4];
    #pragma unroll
    for (int i = 0; i < 2; i++)
        #pragma unroll
        for (int j = 0; j < 4; j++)
            #pragma unroll
            for (int q = 0; q < 4; q++) acc[i][j][q] = 0.f;

    {
        float4 a0 = *(const float4*)Ap;
        float4 b0 = *(const float4*)Bp;
        float4 b1 = *(const float4*)(Bp + (size_t)8 * ldb);
        store_tile_raw(As[0], ar, aq, a0);
        *(float4*)&Bs[0][bk][bn4]     = b0;
        *(float4*)&Bs[0][bk + 8][bn4] = b1;
    }
    __syncthreads();

    const int niter = K / BK;
    int buf = 0;
    float4 pa0, pb0, pb1;

    for (int kt = 0; kt < niter; kt++) {
        const bool has_next = (kt + 1 < niter);
        if (has_next) {
            const float* An = Ap + (kt + 1) * BK;
            pa0 = *(const float4*)An;
            const float* Bn = Bp + (size_t)(kt + 1) * BK * ldb;
            pb0 = *(const float4*)Bn;
            pb1 = *(const float4*)(Bn + (size_t)8 * ldb);
        }

        const unsigned* Ab = As[buf];

        unsigned af[2][2][4];
        #pragma unroll
        for (int mt = 0; mt < 2; mt++) {
            const int r = wm * 32 + mt * 16 + g4;
            uint4 lo = ld_frag_swz(Ab, r,     c);
            uint4 hi = ld_frag_swz(Ab, r + 8, c);
            af[mt][0][0] = lo.x; af[mt][0][1] = hi.x;
            af[mt][0][2] = lo.y; af[mt][0][3] = hi.y;
            af[mt][1][0] = lo.z; af[mt][1][1] = hi.z;
            af[mt][1][2] = lo.w; af[mt][1][3] = hi.w;
        }

        #pragma unroll
        for (int nt = 0; nt < 4; nt++) {
            const int col = wn * 32 + nt * 8 + g4;
            unsigned b0[2] = { Bs[buf][c][col],     Bs[buf][c + 4][col]  };
            unsigned b1[2] = { Bs[buf][c + 8][col], Bs[buf][c + 12][col] };
            #pragma unroll
            for (int mt = 0; mt < 2; mt++) {
                mma_tf32(acc[mt][nt], af[mt][0], b0);
                mma_tf32(acc[mt][nt], af[mt][1], b1);
            }
        }

        if (has_next) {
            store_tile_raw(As[buf ^ 1], ar, aq, pa0);
            *(float4*)&Bs[buf ^ 1][bk][bn4]     = pb0;
            *(float4*)&Bs[buf ^ 1][bk + 8][bn4] = pb1;
        }
        __syncthreads();
        buf ^= 1;
    }

    #pragma unroll
    for (int mt = 0; mt < 2; mt++) {
        const int r0 = m0 + wm * 32 + mt * 16 + g4;
        float il0 = 1.f, il1 = 1.f;
        if (EPI == 1) {
            il0 = rowinv[(size_t)b * SEQ + r0];
            il1 = rowinv[(size_t)b * SEQ + r0 + 8];
        }
        #pragma unroll
        for (int nt = 0; nt < 4; nt++) {
            const int col = n0 + wn * 32 + nt * 8 + 2 * c;
            float2 v0, v1;
            if (EPI == 0) {
                float bx = 0.f, by = 0.f;
                if (bias) { bx = bias[col]; by = bias[col + 1]; }
                v0 = make_float2(acc[mt][nt][0] + bx, acc[mt][nt][1] + by);
                v1 = make_float2(acc[mt][nt][2] + bx, acc[mt][nt][3] + by);
            } else {
                v0 = make_float2(acc[mt][nt][0] * il0, acc[mt][nt][1] * il0);
                v1 = make_float2(acc[mt][nt][2] * il1, acc[mt][nt][3] * il1);
            }
            if (ROUND) {
                v0.x = rnd_tf32(v0.x); v0.y = rnd_tf32(v0.y);
                v1.x = rnd_tf32(v1.x); v1.y = rnd_tf32(v1.y);
            }
            *(float2*)(C + (size_t)r0 * ldc + col) = v0;
            *(float2*)(C + (size_t)(r0 + 8) * ldc + col) = v1;
        }
    }
}

// ------------------------------------------------------------------
// NT score GEMM, fused mask + exp + partial row sums.
// ------------------------------------------------------------------
__global__ void __launch_bounds__(256, 2) mma_nt_exp(
    const float* __restrict__ A, int lda, long long strideA,
    const float* __restrict__ B, int ldb, long long strideB,
    const float* __restrict__ mask,
    float scale,
    float* __restrict__ psum,
    float* __restrict__ C, int ldc, long long strideC,
    int K)
{
    __shared__ unsigned As[2][BM * BK];
    __shared__ unsigned Bs[2][BN * BK];
    __shared__ float   part[BM][8];

    const int b = blockIdx.z;
    A += (size_t)b * strideA;
    B += (size_t)b * strideB;
    C += (size_t)b * strideC;
    const float* mrow = mask + (size_t)b * SEQ;

    const int tid  = threadIdx.x;
    const int lane = tid & 31;
    const int wid  = tid >> 5;
    const int wm = wid & 3;
    const int wn = wid >> 2;
    const int m0 = blockIdx.y * BM;
    const int n0 = blockIdx.x * BN;
    const int c  = lane & 3;
    const int g4 = lane >> 2;

    const int ar = tid >> 2, aq = tid & 3;

    const float* Ap = A + (size_t)(m0 + ar) * lda + 4 * aq;
    const float* Bp = B + (size_t)(n0 + ar) * ldb + 4 * aq;

    float acc[2][8][4];
    #pragma unroll
    for (int i = 0; i < 2; i++)
        #pragma unroll
        for (int j = 0; j < 8; j++)
            #pragma unroll
            for (int q = 0; q < 4; q++) acc[i][j][q] = 0.f;

    {
        float4 a0 = *(const float4*)Ap;
        float4 a1 = *(const float4*)(Ap + (size_t)64 * lda);
        float4 b0 = *(const float4*)Bp;
        float4 b1 = *(const float4*)(Bp + (size_t)64 * ldb);
        store_tile_raw(As[0], ar,      aq, a0);
        store_tile_raw(As[0], ar + 64, aq, a1);
        store_tile_raw(Bs[0], ar,      aq, b0);
        store_tile_raw(Bs[0], ar + 64, aq, b1);
    }
    __syncthreads();

    const int niter = K / BK;
    int buf = 0;
    float4 pa0, pa1, pb0, pb1;

    for (int kt = 0; kt < niter; kt++) {
        const bool has_next = (kt + 1 < niter);
        if (has_next) {
            const float* An = Ap + (kt + 1) * BK;
            pa0 = *(const float4*)An;
            pa1 = *(const float4*)(An + (size_t)64 * lda);
            const float* Bn = Bp + (kt + 1) * BK;
            pb0 = *(const float4*)Bn;
            pb1 = *(const float4*)(Bn + (size_t)64 * ldb);
        }

        const unsigned* Ab = As[buf];
        const unsigned* Bb = Bs[buf];

        unsigned af[2][2][4];
        #pragma unroll
        for (int mt = 0; mt < 2; mt++) {
            const int r = wm * 32 + mt * 16 + g4;
            uint4 lo = ld_frag_swz(Ab, r,     c);
            uint4 hi = ld_frag_swz(Ab, r + 8, c);
            af[mt][0][0] = lo.x; af[mt][0][1] = hi.x;
            af[mt][0][2] = lo.y; af[mt][0][3] = hi.y;
            af[mt][1][0] = lo.z; af[mt][1][1] = hi.z;
            af[mt][1][2] = lo.w; af[mt][1][3] = hi.w;
        }

        #pragma unroll
        for (int nt = 0; nt < 8; nt++) {
            uint4 bv = ld_frag_swz(Bb, wn * 64 + nt * 8 + g4, c);
            unsigned b0[2] = { bv.x, bv.y };
            unsigned b1[2] = { bv.z, bv.w };
            #pragma unroll
            for (int mt = 0; mt < 2; mt++) {
                mma_tf32(acc[mt][nt], af[mt][0], b0);
                mma_tf32(acc[mt][nt], af[mt][1], b1);
            }
        }

        if (has_next) {
            unsigned* An = As[buf ^ 1];
            unsigned* Bn = Bs[buf ^ 1];
            store_tile_raw(An, ar,      aq, pa0);
            store_tile_raw(An, ar + 64, aq, pa1);
            store_tile_raw(Bn, ar,      aq, pb0);
            store_tile_raw(Bn, ar + 64, aq, pb1);
        }
        __syncthreads();
        buf ^= 1;
    }

    // Epilogue: masked exp (tf32-rounded) + write + partial row sums
    #pragma unroll
    for (int mt = 0; mt < 2; mt++) {
        const int r0 = m0 + wm * 32 + mt * 16 + g4;
        const bool rv0 = (mrow[r0] != 0.f);
        const bool rv1 = (mrow[r0 + 8] != 0.f);
        float rs0 = 0.f, rs1 = 0.f;
        #pragma unroll
        for (int nt = 0; nt < 8; nt++) {
            const int col = n0 + wn * 64 + nt * 8 + 2 * c;
            const bool cv0 = (mrow[col] != 0.f);
            const bool cv1 = (mrow[col + 1] != 0.f);
            float2 v0, v1;
            v0.x = rv0 ? (cv0 ? rnd_tf32(__expf(acc[mt][nt][0] * scale)) : 0.f) : 1.f;
            v0.y = rv0 ? (cv1 ? rnd_tf32(__expf(acc[mt][nt][1] * scale)) : 0.f) : 1.f;
            v1.x = rv1 ? (cv0 ? rnd_tf32(__expf(acc[mt][nt][2] * scale)) : 0.f) : 1.f;
            v1.y = rv1 ? (cv1 ? rnd_tf32(__expf(acc[mt][nt][3] * scale)) : 0.f) : 1.f;
            rs0 += v0.x + v0.y;
            rs1 += v1.x + v1.y;
            *(float2*)(C + (size_t)r0 * ldc + col) = v0;
            *(float2*)(C + (size_t)(r0 + 8) * ldc + col) = v1;
        }
        part[wm * 32 + mt * 16 + g4][wn * 4 + c]     = rs0;
        part[wm * 32 + mt * 16 + g4 + 8][wn * 4 + c] = rs1;
    }
    __syncthreads();
    if (tid < BM) {
        float s = 0.f;
        #pragma unroll
        for (int i = 0; i < 8; i++) s += part[tid][i];
        psum[(size_t)blockIdx.x * (BATCH * SEQ) + (size_t)b * SEQ + m0 + tid] = s;
    }
}

// ------------------------------------------------------------------
// Invert summed partials
// ------------------------------------------------------------------
__global__ void __launch_bounds__(256) inv_rows(
    const float* __restrict__ psum, float* __restrict__ rinv)
{
    const int r = blockIdx.x * 256 + threadIdx.x;
    float s = 0.f;
    #pragma unroll
    for (int t = 0; t < 8; t++) s += psum[t * (BATCH * SEQ) + r];
    rinv[r] = 1.0f / s;
}

// ------------------------------------------------------------------
// Launch
// ------------------------------------------------------------------
extern "C" void kernel_launch(void* const* d_in, const int* in_sizes, int n_in,
                              void* d_out, int out_size)
{
    (void)in_sizes; (void)n_in; (void)out_size;

    const float* layout_x = (const float*)d_in[0];
    const float* text_x   = (const float*)d_in[1];
    const float* mask     = (const float*)d_in[2];
    const float* Wqkv     = (const float*)d_in[3];
    const float* bqkv     = (const float*)d_in[4];
    const float* Wq       = (const float*)d_in[5];
    const float* bq       = (const float*)d_in[6];
    const float* Wkv      = (const float*)d_in[7];
    const float* bkv      = (const float*)d_in[8];
    const float* Wffn     = (const float*)d_in[9];
    const float* bffn     = (const float*)d_in[10];
    float* out = (float*)d_out;

    float *qkv, *scores, *lo, *cq, *kv, *merge, *psum, *rinv;
    float *lxr, *txr, *wqkvr, *wqr, *wkvr, *wffnr;
    cudaGetSymbolAddress((void**)&qkv,    g_qkv);
    cudaGetSymbolAddress((void**)&scores, g_scores);
    cudaGetSymbolAddress((void**)&lo,     g_lo);
    cudaGetSymbolAddress((void**)&cq,     g_cq);
    cudaGetSymbolAddress((void**)&kv,     g_kv);
    cudaGetSymbolAddress((void**)&merge,  g_merge);
    cudaGetSymbolAddress((void**)&psum,   g_psum);
    cudaGetSymbolAddress((void**)&rinv,   g_rinv);
    cudaGetSymbolAddress((void**)&lxr,    g_lxr);
    cudaGetSymbolAddress((void**)&txr,    g_txr);
    cudaGetSymbolAddress((void**)&wqkvr,  g_wqkvr);
    cudaGetSymbolAddress((void**)&wqr,    g_wqr);
    cudaGetSymbolAddress((void**)&wkvr,   g_wkvr);
    cudaGetSymbolAddress((void**)&wffnr,  g_wffnr);

    const float scale = rsqrtf((float)CH);
    const dim3 blk(256);
    const long long sQKV = (long long)SEQ * 3 * CH;
    const long long sS   = (long long)SEQ * SEQ;
    const long long sC   = (long long)SEQ * CH;
    const long long sKV  = (long long)SEQ * 2 * CH;

    // 0) tf32 pre-round of all GEMM inputs
    {
        const int nLX = BATCH * SEQ * CH / 4;
        round_tf32<<<(nLX + 255) / 256, blk>>>(layout_x, lxr, nLX);
        round_tf32<<<(nLX + 255) / 256, blk>>>(text_x, txr, nLX);
        const int nWqkv = CH * 3 * CH / 4;
        round_tf32<<<(nWqkv + 255) / 256, blk>>>(Wqkv, wqkvr, nWqkv);
        const int nWq = CH * CH / 4;
        round_tf32<<<(nWq + 255) / 256, blk>>>(Wq, wqr, nWq);
        const int nWkv = CH * 2 * CH / 4;
        round_tf32<<<(nWkv + 255) / 256, blk>>>(Wkv, wkvr, nWkv);
        round_tf32<<<(nWq + 255) / 256, blk>>>(Wffn, wffnr, nWq);
    }

    // 1) qkv = lxr @ Wqkv + bqkv   (rounded output) — BM=128 (deep grid)
    mma_nn<0, true><<<dim3(3 * CH / BN, BATCH * SEQ / BM, 1), blk>>>(
        lxr, CH, 0, wqkvr, 3 * CH, 0, bqkv, nullptr, qkv, 3 * CH, 0, CH);

    // 2) scores = exp(mask(Q @ K^T * scale)) + partial row sums
    mma_nt_exp<<<dim3(SEQ / BN, SEQ / BM, BATCH), blk>>>(
        qkv + 0, 3 * CH, sQKV, qkv + CH, 3 * CH, sQKV, mask, scale,
        psum, scores, SEQ, sS, CH);

    // 3) rinv = 1 / rowsum
    inv_rows<<<BATCH * SEQ / 256, blk>>>(psum, rinv);

    // 4) layout_o = (exp scores @ V) * rinv   — BM=64 (finer waves)
    mma_nn64<1, true><<<dim3(CH / BN, SEQ / 64, BATCH), blk>>>(
        scores, SEQ, sS, qkv + 2 * CH, 3 * CH, sQKV, nullptr, rinv,
        lo, CH, sC, SEQ);

    // 5) cq = lo @ Wq + bq   — BM=64
    mma_nn64<0, true><<<dim3(CH / BN, BATCH * SEQ / 64, 1), blk>>>(
        lo, CH, 0, wqr, CH, 0, bq, nullptr, cq, CH, 0, CH);

    // 6) kv = txr @ Wkv + bkv   — BM=128
    mma_nn<0, true><<<dim3(2 * CH / BN, BATCH * SEQ / BM, 1), blk>>>(
        txr, CH, 0, wkvr, 2 * CH, 0, bkv, nullptr, kv, 2 * CH, 0, CH);

    // 7) scores = exp(mask(CQ @ CK^T * scale)) + partial row sums
    mma_nt_exp<<<dim3(SEQ / BN, SEQ / BM, BATCH), blk>>>(
        cq, CH, sC, kv + 0, 2 * CH, sKV, mask, scale,
        psum, scores, SEQ, sS, CH);

    // 8) rinv
    inv_rows<<<BATCH * SEQ / 256, blk>>>(psum, rinv);

    // 9) merge = (exp scores @ CV) * rinv   — BM=64
    mma_nn64<1, true><<<dim3(CH / BN, SEQ / 64, BATCH), blk>>>(
        scores, SEQ, sS, kv + CH, 2 * CH, sKV, nullptr, rinv,
        merge, CH, sC, SEQ);

    // 10) out = merge @ Wffn + bffn   — BM=64, full f32 output
    mma_nn64<0, false><<<dim3(CH / BN, BATCH * SEQ / 64, 1), blk>>>(
        merge, CH, 0, wffnr, CH, 0, bffn, nullptr, out, CH, 0, CH);
}

// round 12
// speedup vs baseline: 1.0892x; 1.0892x over previous
#include <cuda_runtime.h>
#include <math.h>
#include <stdint.h>

// ------------------------------------------------------------------
// Problem constants: B=8, M=1024, C=768
// ------------------------------------------------------------------
#define BATCH 8
#define SEQ   1024
#define CH    768

// Scratch (device globals; allocation-free per harness rules)
__device__ __align__(16) float g_qkv   [BATCH * SEQ * (3 * CH)];
__device__ __align__(16) float g_scores[BATCH * SEQ * SEQ];   // exp'd scores (tf32-rounded)
__device__ __align__(16) float g_lo    [BATCH * SEQ * CH];
__device__ __align__(16) float g_cq    [BATCH * SEQ * CH];
__device__ __align__(16) float g_kv    [BATCH * SEQ * (2 * CH)];
__device__ __align__(16) float g_merge [BATCH * SEQ * CH];
__device__ __align__(16) float g_psum  [8 * BATCH * SEQ];
__device__ __align__(16) float g_rinv  [BATCH * SEQ];
// tf32-pre-rounded copies of harness inputs
__device__ __align__(16) float g_lxr   [BATCH * SEQ * CH];
__device__ __align__(16) float g_txr   [BATCH * SEQ * CH];
__device__ __align__(16) float g_wqkvr [CH * 3 * CH];
__device__ __align__(16) float g_wqr   [CH * CH];
__device__ __align__(16) float g_wkvr  [CH * 2 * CH];
__device__ __align__(16) float g_wffnr [CH * CH];

#define BM 128
#define BN 128
#define BK 16
#define BNP (BN + 8)

// ------------------------------------------------------------------
// TF32 helpers
// ------------------------------------------------------------------
__device__ __forceinline__ unsigned f2tf32(float x) {
    unsigned u;
    asm("cvt.rna.tf32.f32 %0, %1;" : "=r"(u) : "f"(x));
    return u;
}
__device__ __forceinline__ float rnd_tf32(float x) {
    return __uint_as_float(f2tf32(x));
}

__device__ __forceinline__ void mma_tf32(float* d, const unsigned* a, const unsigned* b) {
    asm volatile(
        "mma.sync.aligned.m16n8k8.row.col.f32.tf32.tf32.f32 "
        "{%0,%1,%2,%3}, {%4,%5,%6,%7}, {%8,%9}, {%0,%1,%2,%3};\n"
        : "+f"(d[0]), "+f"(d[1]), "+f"(d[2]), "+f"(d[3])
        : "r"(a[0]), "r"(a[1]), "r"(a[2]), "r"(a[3]),
          "r"(b[0]), "r"(b[1]));
}

// Swizzled k-major tile storage (RAW bits — inputs pre-rounded):
// flat [row*16 + pos], pos(k,row) = (((k&3)+(row>>1))&3)*4 + (k>>2)
__device__ __forceinline__ void store_tile_raw(unsigned* S, int row, int q, float4 v) {
    const int h = (row >> 1) & 3;
    unsigned* base = S + row * 16 + q;
    base[(((0 + h) & 3) << 2)] = __float_as_uint(v.x);
    base[(((1 + h) & 3) << 2)] = __float_as_uint(v.y);
    base[(((2 + h) & 3) << 2)] = __float_as_uint(v.z);
    base[(((3 + h) & 3) << 2)] = __float_as_uint(v.w);
}

__device__ __forceinline__ uint4 ld_frag_swz(const unsigned* S, int row, int c) {
    const int g = (c + (row >> 1)) & 3;
    return *(const uint4*)(S + row * 16 + (g << 2));
}

// ------------------------------------------------------------------
// Elementwise tf32 rounding
// ------------------------------------------------------------------
__global__ void __launch_bounds__(256) round_tf32(
    const float* __restrict__ in, float* __restrict__ out, int n4)
{
    const int i = blockIdx.x * 256 + threadIdx.x;
    if (i < n4) {
        float4 v = ((const float4*)in)[i];
        v.x = rnd_tf32(v.x); v.y = rnd_tf32(v.y);
        v.z = rnd_tf32(v.z); v.w = rnd_tf32(v.w);
        ((float4*)out)[i] = v;
    }
}

// ------------------------------------------------------------------
// NN (BM=128): C[m,n] = sum_k A[m,k]*B[k,n]; batched via blockIdx.z.
// Warp tile 64x32 (warp grid 2x4): biases frag loads toward the
// vectorized A side (8 LDS.128 + 16 LDS.32 vs old 4 + 32).
// Inputs tf32-pre-rounded; staging stores raw bits.
// EPI = 0: + bias[n];  EPI = 1: * rowinv[row]
// ROUND: epilogue writes tf32-rounded values
// ------------------------------------------------------------------
template<int EPI, bool ROUND>
__global__ void __launch_bounds__(256, 2) mma_nn(
    const float* __restrict__ A, int lda, long long strideA,
    const float* __restrict__ B, int ldb, long long strideB,
    const float* __restrict__ bias,
    const float* __restrict__ rowinv,
    float* __restrict__ C, int ldc, long long strideC,
    int K)
{
    __shared__ unsigned As[2][BM * BK];
    __shared__ unsigned Bs[2][BK][BNP];

    const int b = blockIdx.z;
    A += (size_t)b * strideA;
    B += (size_t)b * strideB;
    C += (size_t)b * strideC;

    const int tid  = threadIdx.x;
    const int lane = tid & 31;
    const int wid  = tid >> 5;
    const int wm = wid & 1;               // 0..1 -> 64-row half
    const int wn = wid >> 1;              // 0..3 -> 32-col quarter
    const int m0 = blockIdx.y * BM;
    const int n0 = blockIdx.x * BN;
    const int c  = lane & 3;
    const int g4 = lane >> 2;

    const int ar = tid >> 2, aq = tid & 3;
    const int bk = tid >> 5, bn4 = (tid & 31) << 2;

    const float* Ap = A + (size_t)(m0 + ar) * lda + 4 * aq;
    const float* Bp = B + (size_t)bk * ldb + n0 + bn4;

    float acc[4][4][4];
    #pragma unroll
    for (int i = 0; i < 4; i++)
        #pragma unroll
        for (int j = 0; j < 4; j++)
            #pragma unroll
            for (int q = 0; q < 4; q++) acc[i][j][q] = 0.f;

    // Prologue: stage k-tile 0 into buffer 0
    {
        float4 a0 = *(const float4*)Ap;
        float4 a1 = *(const float4*)(Ap + (size_t)64 * lda);
        float4 b0 = *(const float4*)Bp;
        float4 b1 = *(const float4*)(Bp + (size_t)8 * ldb);
        store_tile_raw(As[0], ar,      aq, a0);
        store_tile_raw(As[0], ar + 64, aq, a1);
        *(float4*)&Bs[0][bk][bn4]     = b0;
        *(float4*)&Bs[0][bk + 8][bn4] = b1;
    }
    __syncthreads();

    const int niter = K / BK;
    int buf = 0;
    float4 pa0, pa1, pb0, pb1;

    for (int kt = 0; kt < niter; kt++) {
        const bool has_next = (kt + 1 < niter);
        if (has_next) {
            const float* An = Ap + (kt + 1) * BK;
            pa0 = *(const float4*)An;
            pa1 = *(const float4*)(An + (size_t)64 * lda);
            const float* Bn = Bp + (size_t)(kt + 1) * BK * ldb;
            pb0 = *(const float4*)Bn;
            pb1 = *(const float4*)(Bn + (size_t)8 * ldb);
        }

        const unsigned* Ab = As[buf];

        // B fragments first: 4 nt x (2 kgroups x 2 regs) = 16 scalar LDS
        unsigned bf[4][2][2];
        #pragma unroll
        for (int nt = 0; nt < 4; nt++) {
            const int col = wn * 32 + nt * 8 + g4;
            bf[nt][0][0] = Bs[buf][c][col];
            bf[nt][0][1] = Bs[buf][c + 4][col];
            bf[nt][1][0] = Bs[buf][c + 8][col];
            bf[nt][1][1] = Bs[buf][c + 12][col];
        }

        // Per-mt A fragments (2 LDS.128) then 8 MMAs
        #pragma unroll
        for (int mt = 0; mt < 4; mt++) {
            const int r = wm * 64 + mt * 16 + g4;
            uint4 lo = ld_frag_swz(Ab, r,     c);
            uint4 hi = ld_frag_swz(Ab, r + 8, c);
            unsigned af0[4] = { lo.x, hi.x, lo.y, hi.y };
            unsigned af1[4] = { lo.z, hi.z, lo.w, hi.w };
            #pragma unroll
            for (int nt = 0; nt < 4; nt++) {
                mma_tf32(acc[mt][nt], af0, bf[nt][0]);
                mma_tf32(acc[mt][nt], af1, bf[nt][1]);
            }
        }

        if (has_next) {
            unsigned* An = As[buf ^ 1];
            store_tile_raw(An, ar,      aq, pa0);
            store_tile_raw(An, ar + 64, aq, pa1);
            *(float4*)&Bs[buf ^ 1][bk][bn4]     = pb0;
            *(float4*)&Bs[buf ^ 1][bk + 8][bn4] = pb1;
        }
        __syncthreads();
        buf ^= 1;
    }

    #pragma unroll
    for (int mt = 0; mt < 4; mt++) {
        const int r0 = m0 + wm * 64 + mt * 16 + g4;
        float il0 = 1.f, il1 = 1.f;
        if (EPI == 1) {
            il0 = rowinv[(size_t)b * SEQ + r0];
            il1 = rowinv[(size_t)b * SEQ + r0 + 8];
        }
        #pragma unroll
        for (int nt = 0; nt < 4; nt++) {
            const int col = n0 + wn * 32 + nt * 8 + 2 * c;
            float2 v0, v1;
            if (EPI == 0) {
                float bx = 0.f, by = 0.f;
                if (bias) { bx = bias[col]; by = bias[col + 1]; }
                v0 = make_float2(acc[mt][nt][0] + bx, acc[mt][nt][1] + by);
                v1 = make_float2(acc[mt][nt][2] + bx, acc[mt][nt][3] + by);
            } else {
                v0 = make_float2(acc[mt][nt][0] * il0, acc[mt][nt][1] * il0);
                v1 = make_float2(acc[mt][nt][2] * il1, acc[mt][nt][3] * il1);
            }
            if (ROUND) {
                v0.x = rnd_tf32(v0.x); v0.y = rnd_tf32(v0.y);
                v1.x = rnd_tf32(v1.x); v1.y = rnd_tf32(v1.y);
            }
            *(float2*)(C + (size_t)r0 * ldc + col) = v0;
            *(float2*)(C + (size_t)(r0 + 8) * ldc + col) = v1;
        }
    }
}

// ------------------------------------------------------------------
// NT score GEMM, fused mask + exp + partial row sums. (R9-proven)
// ------------------------------------------------------------------
__global__ void __launch_bounds__(256, 2) mma_nt_exp(
    const float* __restrict__ A, int lda, long long strideA,
    const float* __restrict__ B, int ldb, long long strideB,
    const float* __restrict__ mask,
    float scale,
    float* __restrict__ psum,
    float* __restrict__ C, int ldc, long long strideC,
    int K)
{
    __shared__ unsigned As[2][BM * BK];
    __shared__ unsigned Bs[2][BN * BK];
    __shared__ float   part[BM][8];

    const int b = blockIdx.z;
    A += (size_t)b * strideA;
    B += (size_t)b * strideB;
    C += (size_t)b * strideC;
    const float* mrow = mask + (size_t)b * SEQ;

    const int tid  = threadIdx.x;
    const int lane = tid & 31;
    const int wid  = tid >> 5;
    const int wm = wid & 3;
    const int wn = wid >> 2;
    const int m0 = blockIdx.y * BM;
    const int n0 = blockIdx.x * BN;
    const int c  = lane & 3;
    const int g4 = lane >> 2;

    const int ar = tid >> 2, aq = tid & 3;

    const float* Ap = A + (size_t)(m0 + ar) * lda + 4 * aq;
    const float* Bp = B + (size_t)(n0 + ar) * ldb + 4 * aq;

    float acc[2][8][4];
    #pragma unroll
    for (int i = 0; i < 2; i++)
        #pragma unroll
        for (int j = 0; j < 8; j++)
            #pragma unroll
            for (int q = 0; q < 4; q++) acc[i][j][q] = 0.f;

    {
        float4 a0 = *(const float4*)Ap;
        float4 a1 = *(const float4*)(Ap + (size_t)64 * lda);
        float4 b0 = *(const float4*)Bp;
        float4 b1 = *(const float4*)(Bp + (size_t)64 * ldb);
        store_tile_raw(As[0], ar,      aq, a0);
        store_tile_raw(As[0], ar + 64, aq, a1);
        store_tile_raw(Bs[0], ar,      aq, b0);
        store_tile_raw(Bs[0], ar + 64, aq, b1);
    }
    __syncthreads();

    const int niter = K / BK;
    int buf = 0;
    float4 pa0, pa1, pb0, pb1;

    for (int kt = 0; kt < niter; kt++) {
        const bool has_next = (kt + 1 < niter);
        if (has_next) {
            const float* An = Ap + (kt + 1) * BK;
            pa0 = *(const float4*)An;
            pa1 = *(const float4*)(An + (size_t)64 * lda);
            const float* Bn = Bp + (kt + 1) * BK;
            pb0 = *(const float4*)Bn;
            pb1 = *(const float4*)(Bn + (size_t)64 * ldb);
        }

        const unsigned* Ab = As[buf];
        const unsigned* Bb = Bs[buf];

        unsigned af[2][2][4];
        #pragma unroll
        for (int mt = 0; mt < 2; mt++) {
            const int r = wm * 32 + mt * 16 + g4;
            uint4 lo = ld_frag_swz(Ab, r,     c);
            uint4 hi = ld_frag_swz(Ab, r + 8, c);
            af[mt][0][0] = lo.x; af[mt][0][1] = hi.x;
            af[mt][0][2] = lo.y; af[mt][0][3] = hi.y;
            af[mt][1][0] = lo.z; af[mt][1][1] = hi.z;
            af[mt][1][2] = lo.w; af[mt][1][3] = hi.w;
        }

        #pragma unroll
        for (int nt = 0; nt < 8; nt++) {
            uint4 bv = ld_frag_swz(Bb, wn * 64 + nt * 8 + g4, c);
            unsigned b0[2] = { bv.x, bv.y };
            unsigned b1[2] = { bv.z, bv.w };
            #pragma unroll
            for (int mt = 0; mt < 2; mt++) {
                mma_tf32(acc[mt][nt], af[mt][0], b0);
                mma_tf32(acc[mt][nt], af[mt][1], b1);
            }
        }

        if (has_next) {
            unsigned* An = As[buf ^ 1];
            unsigned* Bn = Bs[buf ^ 1];
            store_tile_raw(An, ar,      aq, pa0);
            store_tile_raw(An, ar + 64, aq, pa1);
            store_tile_raw(Bn, ar,      aq, pb0);
            store_tile_raw(Bn, ar + 64, aq, pb1);
        }
        __syncthreads();
        buf ^= 1;
    }

    // Epilogue: masked exp (tf32-rounded) + write + partial row sums
    #pragma unroll
    for (int mt = 0; mt < 2; mt++) {
        const int r0 = m0 + wm * 32 + mt * 16 + g4;
        const bool rv0 = (mrow[r0] != 0.f);
        const bool rv1 = (mrow[r0 + 8] != 0.f);
        float rs0 = 0.f, rs1 = 0.f;
        #pragma unroll
        for (int nt = 0; nt < 8; nt++) {
            const int col = n0 + wn * 64 + nt * 8 + 2 * c;
            const bool cv0 = (mrow[col] != 0.f);
            const bool cv1 = (mrow[col + 1] != 0.f);
            float2 v0, v1;
            v0.x = rv0 ? (cv0 ? rnd_tf32(__expf(acc[mt][nt][0] * scale)) : 0.f) : 1.f;
            v0.y = rv0 ? (cv1 ? rnd_tf32(__expf(acc[mt][nt][1] * scale)) : 0.f) : 1.f;
            v1.x = rv1 ? (cv0 ? rnd_tf32(__expf(acc[mt][nt][2] * scale)) : 0.f) : 1.f;
            v1.y = rv1 ? (cv1 ? rnd_tf32(__expf(acc[mt][nt][3] * scale)) : 0.f) : 1.f;
            rs0 += v0.x + v0.y;
            rs1 += v1.x + v1.y;
            *(float2*)(C + (size_t)r0 * ldc + col) = v0;
            *(float2*)(C + (size_t)(r0 + 8) * ldc + col) = v1;
        }
        part[wm * 32 + mt * 16 + g4][wn * 4 + c]     = rs0;
        part[wm * 32 + mt * 16 + g4 + 8][wn * 4 + c] = rs1;
    }
    __syncthreads();
    if (tid < BM) {
        float s = 0.f;
        #pragma unroll
        for (int i = 0; i < 8; i++) s += part[tid][i];
        psum[(size_t)blockIdx.x * (BATCH * SEQ) + (size_t)b * SEQ + m0 + tid] = s;
    }
}

// ------------------------------------------------------------------
// Invert summed partials
// ------------------------------------------------------------------
__global__ void __launch_bounds__(256) inv_rows(
    const float* __restrict__ psum, float* __restrict__ rinv)
{
    const int r = blockIdx.x * 256 + threadIdx.x;
    float s = 0.f;
    #pragma unroll
    for (int t = 0; t < 8; t++) s += psum[t * (BATCH * SEQ) + r];
    rinv[r] = 1.0f / s;
}

// ------------------------------------------------------------------
// Launch (R9 flow)
// ------------------------------------------------------------------
extern "C" void kernel_launch(void* const* d_in, const int* in_sizes, int n_in,
                              void* d_out, int out_size)
{
    (void)in_sizes; (void)n_in; (void)out_size;

    const float* layout_x = (const float*)d_in[0];
    const float* text_x   = (const float*)d_in[1];
    const float* mask     = (const float*)d_in[2];
    const float* Wqkv     = (const float*)d_in[3];
    const float* bqkv     = (const float*)d_in[4];
    const float* Wq       = (const float*)d_in[5];
    const float* bq       = (const float*)d_in[6];
    const float* Wkv      = (const float*)d_in[7];
    const float* bkv      = (const float*)d_in[8];
    const float* Wffn     = (const float*)d_in[9];
    const float* bffn     = (const float*)d_in[10];
    float* out = (float*)d_out;

    float *qkv, *scores, *lo, *cq, *kv, *merge, *psum, *rinv;
    float *lxr, *txr, *wqkvr, *wqr, *wkvr, *wffnr;
    cudaGetSymbolAddress((void**)&qkv,    g_qkv);
    cudaGetSymbolAddress((void**)&scores, g_scores);
    cudaGetSymbolAddress((void**)&lo,     g_lo);
    cudaGetSymbolAddress((void**)&cq,     g_cq);
    cudaGetSymbolAddress((void**)&kv,     g_kv);
    cudaGetSymbolAddress((void**)&merge,  g_merge);
    cudaGetSymbolAddress((void**)&psum,   g_psum);
    cudaGetSymbolAddress((void**)&rinv,   g_rinv);
    cudaGetSymbolAddress((void**)&lxr,    g_lxr);
    cudaGetSymbolAddress((void**)&txr,    g_txr);
    cudaGetSymbolAddress((void**)&wqkvr,  g_wqkvr);
    cudaGetSymbolAddress((void**)&wqr,    g_wqr);
    cudaGetSymbolAddress((void**)&wkvr,   g_wkvr);
    cudaGetSymbolAddress((void**)&wffnr,  g_wffnr);

    const float scale = rsqrtf((float)CH);
    const dim3 blk(256);
    const long long sQKV = (long long)SEQ * 3 * CH;
    const long long sS   = (long long)SEQ * SEQ;
    const long long sC   = (long long)SEQ * CH;
    const long long sKV  = (long long)SEQ * 2 * CH;

    // 0) tf32 pre-round of all GEMM inputs
    {
        const int nLX = BATCH * SEQ * CH / 4;
        round_tf32<<<(nLX + 255) / 256, blk>>>(layout_x, lxr, nLX);
        round_tf32<<<(nLX + 255) / 256, blk>>>(text_x, txr, nLX);
        const int nWqkv = CH * 3 * CH / 4;
        round_tf32<<<(nWqkv + 255) / 256, blk>>>(Wqkv, wqkvr, nWqkv);
        const int nWq = CH * CH / 4;
        round_tf32<<<(nWq + 255) / 256, blk>>>(Wq, wqr, nWq);
        const int nWkv = CH * 2 * CH / 4;
        round_tf32<<<(nWkv + 255) / 256, blk>>>(Wkv, wkvr, nWkv);
        round_tf32<<<(nWq + 255) / 256, blk>>>(Wffn, wffnr, nWq);
    }

    // 1) qkv = lxr @ Wqkv + bqkv   (rounded output)
    mma_nn<0, true><<<dim3(3 * CH / BN, BATCH * SEQ / BM, 1), blk>>>(
        lxr, CH, 0, wqkvr, 3 * CH, 0, bqkv, nullptr, qkv, 3 * CH, 0, CH);

    // 2) scores = exp(mask(Q @ K^T * scale)) + partial row sums
    mma_nt_exp<<<dim3(SEQ / BN, SEQ / BM, BATCH), blk>>>(
        qkv + 0, 3 * CH, sQKV, qkv + CH, 3 * CH, sQKV, mask, scale,
        psum, scores, SEQ, sS, CH);

    // 3) rinv = 1 / rowsum
    inv_rows<<<BATCH * SEQ / 256, blk>>>(psum, rinv);

    // 4) layout_o = (exp scores @ V) * rinv   (rounded output)
    mma_nn<1, true><<<dim3(CH / BN, SEQ / BM, BATCH), blk>>>(
        scores, SEQ, sS, qkv + 2 * CH, 3 * CH, sQKV, nullptr, rinv,
        lo, CH, sC, SEQ);

    // 5) cq = lo @ Wq + bq   (rounded output)
    mma_nn<0, true><<<dim3(CH / BN, BATCH * SEQ / BM, 1), blk>>>(
        lo, CH, 0, wqr, CH, 0, bq, nullptr, cq, CH, 0, CH);

    // 6) kv = txr @ Wkv + bkv   (rounded output)
    mma_nn<0, true><<<dim3(2 * CH / BN, BATCH * SEQ / BM, 1), blk>>>(
        txr, CH, 0, wkvr, 2 * CH, 0, bkv, nullptr, kv, 2 * CH, 0, CH);

    // 7) scores = exp(mask(CQ @ CK^T * scale)) + partial row sums
    mma_nt_exp<<<dim3(SEQ / BN, SEQ / BM, BATCH), blk>>>(
        cq, CH, sC, kv + 0, 2 * CH, sKV, mask, scale,
        psum, scores, SEQ, sS, CH);

    // 8) rinv
    inv_rows<<<BATCH * SEQ / 256, blk>>>(psum, rinv);

    // 9) merge = (exp scores @ CV) * rinv   (rounded output)
    mma_nn<1, true><<<dim3(CH / BN, SEQ / BM, BATCH), blk>>>(
        scores, SEQ, sS, kv + CH, 2 * CH, sKV, nullptr, rinv,
        merge, CH, sC, SEQ);

    // 10) out = merge @ Wffn + bffn   (full f32 output)
    mma_nn<0, false><<<dim3(CH / BN, BATCH * SEQ / BM, 1), blk>>>(
        merge, CH, 0, wffnr, CH, 0, bffn, nullptr, out, CH, 0, CH);
}

// round 13
// speedup vs baseline: 1.1390x; 1.0457x over previous
#include <cuda_runtime.h>
#include <math.h>
#include <stdint.h>

// ------------------------------------------------------------------
// Problem constants: B=8, M=1024, C=768
// ------------------------------------------------------------------
#define BATCH 8
#define SEQ   1024
#define CH    768

// Scratch (device globals; allocation-free per harness rules)
__device__ __align__(16) float g_qkv   [BATCH * SEQ * (3 * CH)];
__device__ __align__(16) float g_scores[BATCH * SEQ * SEQ];   // exp'd scores (tf32-rounded)
__device__ __align__(16) float g_lo    [BATCH * SEQ * CH];
__device__ __align__(16) float g_cq    [BATCH * SEQ * CH];
__device__ __align__(16) float g_kv    [BATCH * SEQ * (2 * CH)];
__device__ __align__(16) float g_merge [BATCH * SEQ * CH];
__device__ __align__(16) float g_psum  [8 * BATCH * SEQ];
__device__ __align__(16) float g_rinv  [BATCH * SEQ];
// tf32-pre-rounded copies of harness inputs
__device__ __align__(16) float g_lxr   [BATCH * SEQ * CH];
__device__ __align__(16) float g_txr   [BATCH * SEQ * CH];
__device__ __align__(16) float g_wqkvr [CH * 3 * CH];
__device__ __align__(16) float g_wqr   [CH * CH];
__device__ __align__(16) float g_wkvr  [CH * 2 * CH];
__device__ __align__(16) float g_wffnr [CH * CH];

#define BM 128
#define BN 128
#define BK 16
#define BNP (BN + 8)

// ------------------------------------------------------------------
// TF32 helpers
// ------------------------------------------------------------------
__device__ __forceinline__ unsigned f2tf32(float x) {
    unsigned u;
    asm("cvt.rna.tf32.f32 %0, %1;" : "=r"(u) : "f"(x));
    return u;
}
__device__ __forceinline__ float rnd_tf32(float x) {
    return __uint_as_float(f2tf32(x));
}

__device__ __forceinline__ void mma_tf32(float* d, const unsigned* a, const unsigned* b) {
    asm volatile(
        "mma.sync.aligned.m16n8k8.row.col.f32.tf32.tf32.f32 "
        "{%0,%1,%2,%3}, {%4,%5,%6,%7}, {%8,%9}, {%0,%1,%2,%3};\n"
        : "+f"(d[0]), "+f"(d[1]), "+f"(d[2]), "+f"(d[3])
        : "r"(a[0]), "r"(a[1]), "r"(a[2]), "r"(a[3]),
          "r"(b[0]), "r"(b[1]));
}

// Swizzled k-major tile storage (RAW bits — inputs pre-rounded):
// flat [row*16 + pos], pos(k,row) = (((k&3)+(row>>1))&3)*4 + (k>>2)
__device__ __forceinline__ void store_tile_raw(unsigned* S, int row, int q, float4 v) {
    const int h = (row >> 1) & 3;
    unsigned* base = S + row * 16 + q;
    base[(((0 + h) & 3) << 2)] = __float_as_uint(v.x);
    base[(((1 + h) & 3) << 2)] = __float_as_uint(v.y);
    base[(((2 + h) & 3) << 2)] = __float_as_uint(v.z);
    base[(((3 + h) & 3) << 2)] = __float_as_uint(v.w);
}

__device__ __forceinline__ uint4 ld_frag_swz(const unsigned* S, int row, int c) {
    const int g = (c + (row >> 1)) & 3;
    return *(const uint4*)(S + row * 16 + (g << 2));
}

// ------------------------------------------------------------------
// Elementwise tf32 rounding
// ------------------------------------------------------------------
__global__ void __launch_bounds__(256) round_tf32(
    const float* __restrict__ in, float* __restrict__ out, int n4)
{
    const int i = blockIdx.x * 256 + threadIdx.x;
    if (i < n4) {
        float4 v = ((const float4*)in)[i];
        v.x = rnd_tf32(v.x); v.y = rnd_tf32(v.y);
        v.z = rnd_tf32(v.z); v.w = rnd_tf32(v.w);
        ((float4*)out)[i] = v;
    }
}

// ------------------------------------------------------------------
// NN (BM=128): C[m,n] = sum_k A[m,k]*B[k,n]; batched via blockIdx.z.
// Warp tile 64x32 (warp grid 2x4). Inputs tf32-pre-rounded.
// EPI = 0: + bias[n];  EPI = 1: * rowinv[row]
// ROUND: epilogue writes tf32-rounded values
// ------------------------------------------------------------------
template<int EPI, bool ROUND>
__global__ void __launch_bounds__(256, 2) mma_nn(
    const float* __restrict__ A, int lda, long long strideA,
    const float* __restrict__ B, int ldb, long long strideB,
    const float* __restrict__ bias,
    const float* __restrict__ rowinv,
    float* __restrict__ C, int ldc, long long strideC,
    int K)
{
    __shared__ unsigned As[2][BM * BK];
    __shared__ unsigned Bs[2][BK][BNP];

    const int b = blockIdx.z;
    A += (size_t)b * strideA;
    B += (size_t)b * strideB;
    C += (size_t)b * strideC;

    const int tid  = threadIdx.x;
    const int lane = tid & 31;
    const int wid  = tid >> 5;
    const int wm = wid & 1;
    const int wn = wid >> 1;
    const int m0 = blockIdx.y * BM;
    const int n0 = blockIdx.x * BN;
    const int c  = lane & 3;
    const int g4 = lane >> 2;

    const int ar = tid >> 2, aq = tid & 3;
    const int bk = tid >> 5, bn4 = (tid & 31) << 2;

    const float* Ap = A + (size_t)(m0 + ar) * lda + 4 * aq;
    const float* Bp = B + (size_t)bk * ldb + n0 + bn4;

    float acc[4][4][4];
    #pragma unroll
    for (int i = 0; i < 4; i++)
        #pragma unroll
        for (int j = 0; j < 4; j++)
            #pragma unroll
            for (int q = 0; q < 4; q++) acc[i][j][q] = 0.f;

    {
        float4 a0 = *(const float4*)Ap;
        float4 a1 = *(const float4*)(Ap + (size_t)64 * lda);
        float4 b0 = *(const float4*)Bp;
        float4 b1 = *(const float4*)(Bp + (size_t)8 * ldb);
        store_tile_raw(As[0], ar,      aq, a0);
        store_tile_raw(As[0], ar + 64, aq, a1);
        *(float4*)&Bs[0][bk][bn4]     = b0;
        *(float4*)&Bs[0][bk + 8][bn4] = b1;
    }
    __syncthreads();

    const int niter = K / BK;
    int buf = 0;
    float4 pa0, pa1, pb0, pb1;

    for (int kt = 0; kt < niter; kt++) {
        const bool has_next = (kt + 1 < niter);
        if (has_next) {
            const float* An = Ap + (kt + 1) * BK;
            pa0 = *(const float4*)An;
            pa1 = *(const float4*)(An + (size_t)64 * lda);
            const float* Bn = Bp + (size_t)(kt + 1) * BK * ldb;
            pb0 = *(const float4*)Bn;
            pb1 = *(const float4*)(Bn + (size_t)8 * ldb);
        }

        const unsigned* Ab = As[buf];

        unsigned bf[4][2][2];
        #pragma unroll
        for (int nt = 0; nt < 4; nt++) {
            const int col = wn * 32 + nt * 8 + g4;
            bf[nt][0][0] = Bs[buf][c][col];
            bf[nt][0][1] = Bs[buf][c + 4][col];
            bf[nt][1][0] = Bs[buf][c + 8][col];
            bf[nt][1][1] = Bs[buf][c + 12][col];
        }

        #pragma unroll
        for (int mt = 0; mt < 4; mt++) {
            const int r = wm * 64 + mt * 16 + g4;
            uint4 lo = ld_frag_swz(Ab, r,     c);
            uint4 hi = ld_frag_swz(Ab, r + 8, c);
            unsigned af0[4] = { lo.x, hi.x, lo.y, hi.y };
            unsigned af1[4] = { lo.z, hi.z, lo.w, hi.w };
            #pragma unroll
            for (int nt = 0; nt < 4; nt++) {
                mma_tf32(acc[mt][nt], af0, bf[nt][0]);
                mma_tf32(acc[mt][nt], af1, bf[nt][1]);
            }
        }

        if (has_next) {
            unsigned* An = As[buf ^ 1];
            store_tile_raw(An, ar,      aq, pa0);
            store_tile_raw(An, ar + 64, aq, pa1);
            *(float4*)&Bs[buf ^ 1][bk][bn4]     = pb0;
            *(float4*)&Bs[buf ^ 1][bk + 8][bn4] = pb1;
        }
        __syncthreads();
        buf ^= 1;
    }

    #pragma unroll
    for (int mt = 0; mt < 4; mt++) {
        const int r0 = m0 + wm * 64 + mt * 16 + g4;
        float il0 = 1.f, il1 = 1.f;
        if (EPI == 1) {
            il0 = rowinv[(size_t)b * SEQ + r0];
            il1 = rowinv[(size_t)b * SEQ + r0 + 8];
        }
        #pragma unroll
        for (int nt = 0; nt < 4; nt++) {
            const int col = n0 + wn * 32 + nt * 8 + 2 * c;
            float2 v0, v1;
            if (EPI == 0) {
                float bx = 0.f, by = 0.f;
                if (bias) { bx = bias[col]; by = bias[col + 1]; }
                v0 = make_float2(acc[mt][nt][0] + bx, acc[mt][nt][1] + by);
                v1 = make_float2(acc[mt][nt][2] + bx, acc[mt][nt][3] + by);
            } else {
                v0 = make_float2(acc[mt][nt][0] * il0, acc[mt][nt][1] * il0);
                v1 = make_float2(acc[mt][nt][2] * il1, acc[mt][nt][3] * il1);
            }
            if (ROUND) {
                v0.x = rnd_tf32(v0.x); v0.y = rnd_tf32(v0.y);
                v1.x = rnd_tf32(v1.x); v1.y = rnd_tf32(v1.y);
            }
            *(float2*)(C + (size_t)r0 * ldc + col) = v0;
            *(float2*)(C + (size_t)(r0 + 8) * ldc + col) = v1;
        }
    }
}

// ------------------------------------------------------------------
// NT score GEMM, fused mask + exp + partial row sums. (R9-proven)
// ------------------------------------------------------------------
__global__ void __launch_bounds__(256, 2) mma_nt_exp(
    const float* __restrict__ A, int lda, long long strideA,
    const float* __restrict__ B, int ldb, long long strideB,
    const float* __restrict__ mask,
    float scale,
    float* __restrict__ psum,
    float* __restrict__ C, int ldc, long long strideC,
    int K)
{
    __shared__ unsigned As[2][BM * BK];
    __shared__ unsigned Bs[2][BN * BK];
    __shared__ float   part[BM][8];

    const int b = blockIdx.z;
    A += (size_t)b * strideA;
    B += (size_t)b * strideB;
    C += (size_t)b * strideC;
    const float* mrow = mask + (size_t)b * SEQ;

    const int tid  = threadIdx.x;
    const int lane = tid & 31;
    const int wid  = tid >> 5;
    const int wm = wid & 3;
    const int wn = wid >> 2;
    const int m0 = blockIdx.y * BM;
    const int n0 = blockIdx.x * BN;
    const int c  = lane & 3;
    const int g4 = lane >> 2;

    const int ar = tid >> 2, aq = tid & 3;

    const float* Ap = A + (size_t)(m0 + ar) * lda + 4 * aq;
    const float* Bp = B + (size_t)(n0 + ar) * ldb + 4 * aq;

    float acc[2][8][4];
    #pragma unroll
    for (int i = 0; i < 2; i++)
        #pragma unroll
        for (int j = 0; j < 8; j++)
            #pragma unroll
            for (int q = 0; q < 4; q++) acc[i][j][q] = 0.f;

    {
        float4 a0 = *(const float4*)Ap;
        float4 a1 = *(const float4*)(Ap + (size_t)64 * lda);
        float4 b0 = *(const float4*)Bp;
        float4 b1 = *(const float4*)(Bp + (size_t)64 * ldb);
        store_tile_raw(As[0], ar,      aq, a0);
        store_tile_raw(As[0], ar + 64, aq, a1);
        store_tile_raw(Bs[0], ar,      aq, b0);
        store_tile_raw(Bs[0], ar + 64, aq, b1);
    }
    __syncthreads();

    const int niter = K / BK;
    int buf = 0;
    float4 pa0, pa1, pb0, pb1;

    for (int kt = 0; kt < niter; kt++) {
        const bool has_next = (kt + 1 < niter);
        if (has_next) {
            const float* An = Ap + (kt + 1) * BK;
            pa0 = *(const float4*)An;
            pa1 = *(const float4*)(An + (size_t)64 * lda);
            const float* Bn = Bp + (kt + 1) * BK;
            pb0 = *(const float4*)Bn;
            pb1 = *(const float4*)(Bn + (size_t)64 * ldb);
        }

        const unsigned* Ab = As[buf];
        const unsigned* Bb = Bs[buf];

        unsigned af[2][2][4];
        #pragma unroll
        for (int mt = 0; mt < 2; mt++) {
            const int r = wm * 32 + mt * 16 + g4;
            uint4 lo = ld_frag_swz(Ab, r,     c);
            uint4 hi = ld_frag_swz(Ab, r + 8, c);
            af[mt][0][0] = lo.x; af[mt][0][1] = hi.x;
            af[mt][0][2] = lo.y; af[mt][0][3] = hi.y;
            af[mt][1][0] = lo.z; af[mt][1][1] = hi.z;
            af[mt][1][2] = lo.w; af[mt][1][3] = hi.w;
        }

        #pragma unroll
        for (int nt = 0; nt < 8; nt++) {
            uint4 bv = ld_frag_swz(Bb, wn * 64 + nt * 8 + g4, c);
            unsigned b0[2] = { bv.x, bv.y };
            unsigned b1[2] = { bv.z, bv.w };
            #pragma unroll
            for (int mt = 0; mt < 2; mt++) {
                mma_tf32(acc[mt][nt], af[mt][0], b0);
                mma_tf32(acc[mt][nt], af[mt][1], b1);
            }
        }

        if (has_next) {
            unsigned* An = As[buf ^ 1];
            unsigned* Bn = Bs[buf ^ 1];
            store_tile_raw(An, ar,      aq, pa0);
            store_tile_raw(An, ar + 64, aq, pa1);
            store_tile_raw(Bn, ar,      aq, pb0);
            store_tile_raw(Bn, ar + 64, aq, pb1);
        }
        __syncthreads();
        buf ^= 1;
    }

    // Epilogue: masked exp (tf32-rounded) + write + partial row sums
    #pragma unroll
    for (int mt = 0; mt < 2; mt++) {
        const int r0 = m0 + wm * 32 + mt * 16 + g4;
        const bool rv0 = (mrow[r0] != 0.f);
        const bool rv1 = (mrow[r0 + 8] != 0.f);
        float rs0 = 0.f, rs1 = 0.f;
        #pragma unroll
        for (int nt = 0; nt < 8; nt++) {
            const int col = n0 + wn * 64 + nt * 8 + 2 * c;
            const bool cv0 = (mrow[col] != 0.f);
            const bool cv1 = (mrow[col + 1] != 0.f);
            float2 v0, v1;
            v0.x = rv0 ? (cv0 ? rnd_tf32(__expf(acc[mt][nt][0] * scale)) : 0.f) : 1.f;
            v0.y = rv0 ? (cv1 ? rnd_tf32(__expf(acc[mt][nt][1] * scale)) : 0.f) : 1.f;
            v1.x = rv1 ? (cv0 ? rnd_tf32(__expf(acc[mt][nt][2] * scale)) : 0.f) : 1.f;
            v1.y = rv1 ? (cv1 ? rnd_tf32(__expf(acc[mt][nt][3] * scale)) : 0.f) : 1.f;
            rs0 += v0.x + v0.y;
            rs1 += v1.x + v1.y;
            *(float2*)(C + (size_t)r0 * ldc + col) = v0;
            *(float2*)(C + (size_t)(r0 + 8) * ldc + col) = v1;
        }
        part[wm * 32 + mt * 16 + g4][wn * 4 + c]     = rs0;
        part[wm * 32 + mt * 16 + g4 + 8][wn * 4 + c] = rs1;
    }
    __syncthreads();
    if (tid < BM) {
        float s = 0.f;
        #pragma unroll
        for (int i = 0; i < 8; i++) s += part[tid][i];
        psum[(size_t)blockIdx.x * (BATCH * SEQ) + (size_t)b * SEQ + m0 + tid] = s;
    }
}

// ------------------------------------------------------------------
// Invert summed partials
// ------------------------------------------------------------------
__global__ void __launch_bounds__(256) inv_rows(
    const float* __restrict__ psum, float* __restrict__ rinv)
{
    const int r = blockIdx.x * 256 + threadIdx.x;
    float s = 0.f;
    #pragma unroll
    for (int t = 0; t < 8; t++) s += psum[t * (BATCH * SEQ) + r];
    rinv[r] = 1.0f / s;
}

// ------------------------------------------------------------------
// Launch (R12 flow + side-stream fork for the independent kv branch)
// ------------------------------------------------------------------
extern "C" void kernel_launch(void* const* d_in, const int* in_sizes, int n_in,
                              void* d_out, int out_size)
{
    (void)in_sizes; (void)n_in; (void)out_size;

    const float* layout_x = (const float*)d_in[0];
    const float* text_x   = (const float*)d_in[1];
    const float* mask     = (const float*)d_in[2];
    const float* Wqkv     = (const float*)d_in[3];
    const float* bqkv     = (const float*)d_in[4];
    const float* Wq       = (const float*)d_in[5];
    const float* bq       = (const float*)d_in[6];
    const float* Wkv      = (const float*)d_in[7];
    const float* bkv      = (const float*)d_in[8];
    const float* Wffn     = (const float*)d_in[9];
    const float* bffn     = (const float*)d_in[10];
    float* out = (float*)d_out;

    float *qkv, *scores, *lo, *cq, *kv, *merge, *psum, *rinv;
    float *lxr, *txr, *wqkvr, *wqr, *wkvr, *wffnr;
    cudaGetSymbolAddress((void**)&qkv,    g_qkv);
    cudaGetSymbolAddress((void**)&scores, g_scores);
    cudaGetSymbolAddress((void**)&lo,     g_lo);
    cudaGetSymbolAddress((void**)&cq,     g_cq);
    cudaGetSymbolAddress((void**)&kv,     g_kv);
    cudaGetSymbolAddress((void**)&merge,  g_merge);
    cudaGetSymbolAddress((void**)&psum,   g_psum);
    cudaGetSymbolAddress((void**)&rinv,   g_rinv);
    cudaGetSymbolAddress((void**)&lxr,    g_lxr);
    cudaGetSymbolAddress((void**)&txr,    g_txr);
    cudaGetSymbolAddress((void**)&wqkvr,  g_wqkvr);
    cudaGetSymbolAddress((void**)&wqr,    g_wqr);
    cudaGetSymbolAddress((void**)&wkvr,   g_wkvr);
    cudaGetSymbolAddress((void**)&wffnr,  g_wffnr);

    // Side stream + fork/join events (created once; host-side objects only)
    static cudaStream_t s_side = nullptr;
    static cudaEvent_t ev_fork = nullptr, ev_join = nullptr;
    if (s_side == nullptr) {
        cudaStreamCreateWithFlags(&s_side, cudaStreamNonBlocking);
        cudaEventCreateWithFlags(&ev_fork, cudaEventDisableTiming);
        cudaEventCreateWithFlags(&ev_join, cudaEventDisableTiming);
    }

    const float scale = rsqrtf((float)CH);
    const dim3 blk(256);
    const long long sQKV = (long long)SEQ * 3 * CH;
    const long long sS   = (long long)SEQ * SEQ;
    const long long sC   = (long long)SEQ * CH;
    const long long sKV  = (long long)SEQ * 2 * CH;

    // ---- fork: side branch = {round(text_x), round(Wkv), kv GEMM} ----
    cudaEventRecord(ev_fork, 0);
    cudaStreamWaitEvent(s_side, ev_fork, 0);

    {
        const int nLX = BATCH * SEQ * CH / 4;
        round_tf32<<<(nLX + 255) / 256, blk, 0, s_side>>>(text_x, txr, nLX);
        const int nWkv = CH * 2 * CH / 4;
        round_tf32<<<(nWkv + 255) / 256, blk, 0, s_side>>>(Wkv, wkvr, nWkv);
        // kv = txr @ Wkv + bkv   (rounded output)
        mma_nn<0, true><<<dim3(2 * CH / BN, BATCH * SEQ / BM, 1), blk, 0, s_side>>>(
            txr, CH, 0, wkvr, 2 * CH, 0, bkv, nullptr, kv, 2 * CH, 0, CH);
    }
    cudaEventRecord(ev_join, s_side);

    // ---- main chain ----
    {
        const int nLX = BATCH * SEQ * CH / 4;
        round_tf32<<<(nLX + 255) / 256, blk>>>(layout_x, lxr, nLX);
        const int nWqkv = CH * 3 * CH / 4;
        round_tf32<<<(nWqkv + 255) / 256, blk>>>(Wqkv, wqkvr, nWqkv);
        const int nWq = CH * CH / 4;
        round_tf32<<<(nWq + 255) / 256, blk>>>(Wq, wqr, nWq);
        round_tf32<<<(nWq + 255) / 256, blk>>>(Wffn, wffnr, nWq);
    }

    // 1) qkv = lxr @ Wqkv + bqkv   (rounded output)
    mma_nn<0, true><<<dim3(3 * CH / BN, BATCH * SEQ / BM, 1), blk>>>(
        lxr, CH, 0, wqkvr, 3 * CH, 0, bqkv, nullptr, qkv, 3 * CH, 0, CH);

    // 2) scores = exp(mask(Q @ K^T * scale)) + partial row sums
    mma_nt_exp<<<dim3(SEQ / BN, SEQ / BM, BATCH), blk>>>(
        qkv + 0, 3 * CH, sQKV, qkv + CH, 3 * CH, sQKV, mask, scale,
        psum, scores, SEQ, sS, CH);

    // 3) rinv = 1 / rowsum
    inv_rows<<<BATCH * SEQ / 256, blk>>>(psum, rinv);

    // 4) layout_o = (exp scores @ V) * rinv   (rounded output)
    mma_nn<1, true><<<dim3(CH / BN, SEQ / BM, BATCH), blk>>>(
        scores, SEQ, sS, qkv + 2 * CH, 3 * CH, sQKV, nullptr, rinv,
        lo, CH, sC, SEQ);

    // 5) cq = lo @ Wq + bq   (rounded output)
    mma_nn<0, true><<<dim3(CH / BN, BATCH * SEQ / BM, 1), blk>>>(
        lo, CH, 0, wqr, CH, 0, bq, nullptr, cq, CH, 0, CH);

    // ---- join: cross-attention needs kv from the side branch ----
    cudaStreamWaitEvent(0, ev_join, 0);

    // 7) scores = exp(mask(CQ @ CK^T * scale)) + partial row sums
    mma_nt_exp<<<dim3(SEQ / BN, SEQ / BM, BATCH), blk>>>(
        cq, CH, sC, kv + 0, 2 * CH, sKV, mask, scale,
        psum, scores, SEQ, sS, CH);

    // 8) rinv
    inv_rows<<<BATCH * SEQ / 256, blk>>>(psum, rinv);

    // 9) merge = (exp scores @ CV) * rinv   (rounded output)
    mma_nn<1, true><<<dim3(CH / BN, SEQ / BM, BATCH), blk>>>(
        scores, SEQ, sS, kv + CH, 2 * CH, sKV, nullptr, rinv,
        merge, CH, sC, SEQ);

    // 10) out = merge @ Wffn + bffn   (full f32 output)
    mma_nn<0, false><<<dim3(CH / BN, BATCH * SEQ / BM, 1), blk>>>(
        merge, CH, 0, wffnr, CH, 0, bffn, nullptr, out, CH, 0, CH);
}

// round 14
// speedup vs baseline: 1.1558x; 1.0147x over previous
#include <cuda_runtime.h>
#include <math.h>
#include <stdint.h>

// ------------------------------------------------------------------
// Problem constants: B=8, M=1024, C=768
// ------------------------------------------------------------------
#define BATCH 8
#define SEQ   1024
#define CH    768

// Scratch (device globals; allocation-free per harness rules)
__device__ __align__(16) float g_qkv   [BATCH * SEQ * (3 * CH)];
__device__ __align__(16) float g_scores[BATCH * SEQ * SEQ];   // exp'd scores (tf32-rounded)
__device__ __align__(16) float g_lo    [BATCH * SEQ * CH];
__device__ __align__(16) float g_cq    [BATCH * SEQ * CH];
__device__ __align__(16) float g_kv    [BATCH * SEQ * (2 * CH)];
__device__ __align__(16) float g_merge [BATCH * SEQ * CH];
__device__ __align__(16) float g_psum  [8 * BATCH * SEQ];
// tf32-pre-rounded copies of harness inputs
__device__ __align__(16) float g_lxr   [BATCH * SEQ * CH];
__device__ __align__(16) float g_txr   [BATCH * SEQ * CH];
__device__ __align__(16) float g_wqkvr [CH * 3 * CH];
__device__ __align__(16) float g_wqr   [CH * CH];
__device__ __align__(16) float g_wkvr  [CH * 2 * CH];
__device__ __align__(16) float g_wffnr [CH * CH];

#define BM 128
#define BN 128
#define BK 16
#define BNP (BN + 8)

// ------------------------------------------------------------------
// TF32 helpers
// ------------------------------------------------------------------
__device__ __forceinline__ unsigned f2tf32(float x) {
    unsigned u;
    asm("cvt.rna.tf32.f32 %0, %1;" : "=r"(u) : "f"(x));
    return u;
}
__device__ __forceinline__ float rnd_tf32(float x) {
    return __uint_as_float(f2tf32(x));
}

__device__ __forceinline__ void mma_tf32(float* d, const unsigned* a, const unsigned* b) {
    asm volatile(
        "mma.sync.aligned.m16n8k8.row.col.f32.tf32.tf32.f32 "
        "{%0,%1,%2,%3}, {%4,%5,%6,%7}, {%8,%9}, {%0,%1,%2,%3};\n"
        : "+f"(d[0]), "+f"(d[1]), "+f"(d[2]), "+f"(d[3])
        : "r"(a[0]), "r"(a[1]), "r"(a[2]), "r"(a[3]),
          "r"(b[0]), "r"(b[1]));
}

// Swizzled k-major tile storage (RAW bits — inputs pre-rounded):
// flat [row*16 + pos], pos(k,row) = (((k&3)+(row>>1))&3)*4 + (k>>2)
__device__ __forceinline__ void store_tile_raw(unsigned* S, int row, int q, float4 v) {
    const int h = (row >> 1) & 3;
    unsigned* base = S + row * 16 + q;
    base[(((0 + h) & 3) << 2)] = __float_as_uint(v.x);
    base[(((1 + h) & 3) << 2)] = __float_as_uint(v.y);
    base[(((2 + h) & 3) << 2)] = __float_as_uint(v.z);
    base[(((3 + h) & 3) << 2)] = __float_as_uint(v.w);
}

__device__ __forceinline__ uint4 ld_frag_swz(const unsigned* S, int row, int c) {
    const int g = (c + (row >> 1)) & 3;
    return *(const uint4*)(S + row * 16 + (g << 2));
}

// ------------------------------------------------------------------
// Elementwise tf32 rounding
// ------------------------------------------------------------------
__global__ void __launch_bounds__(256) round_tf32(
    const float* __restrict__ in, float* __restrict__ out, int n4)
{
    const int i = blockIdx.x * 256 + threadIdx.x;
    if (i < n4) {
        float4 v = ((const float4*)in)[i];
        v.x = rnd_tf32(v.x); v.y = rnd_tf32(v.y);
        v.z = rnd_tf32(v.z); v.w = rnd_tf32(v.w);
        ((float4*)out)[i] = v;
    }
}

// ------------------------------------------------------------------
// NN (BM=128): C[m,n] = sum_k A[m,k]*B[k,n]; batched via blockIdx.z.
// Warp tile 64x32 (warp grid 2x4). Inputs tf32-pre-rounded.
// EPI = 0: + bias[n]
// EPI = 1: softmax normalize — "aux" points at psum[8][BATCH*SEQ];
//          CTA cooperatively folds the 8 partials into 1/rowsum.
// ROUND: epilogue writes tf32-rounded values
// ------------------------------------------------------------------
template<int EPI, bool ROUND>
__global__ void __launch_bounds__(256, 2) mma_nn(
    const float* __restrict__ A, int lda, long long strideA,
    const float* __restrict__ B, int ldb, long long strideB,
    const float* __restrict__ bias,
    const float* __restrict__ aux,
    float* __restrict__ C, int ldc, long long strideC,
    int K)
{
    __shared__ unsigned As[2][BM * BK];
    __shared__ unsigned Bs[2][BK][BNP];
    __shared__ float    rinv_s[BM];

    const int b = blockIdx.z;
    A += (size_t)b * strideA;
    B += (size_t)b * strideB;
    C += (size_t)b * strideC;

    const int tid  = threadIdx.x;
    const int lane = tid & 31;
    const int wid  = tid >> 5;
    const int wm = wid & 1;
    const int wn = wid >> 1;
    const int m0 = blockIdx.y * BM;
    const int n0 = blockIdx.x * BN;
    const int c  = lane & 3;
    const int g4 = lane >> 2;

    const int ar = tid >> 2, aq = tid & 3;
    const int bk = tid >> 5, bn4 = (tid & 31) << 2;

    const float* Ap = A + (size_t)(m0 + ar) * lda + 4 * aq;
    const float* Bp = B + (size_t)bk * ldb + n0 + bn4;

    float acc[4][4][4];
    #pragma unroll
    for (int i = 0; i < 4; i++)
        #pragma unroll
        for (int j = 0; j < 4; j++)
            #pragma unroll
            for (int q = 0; q < 4; q++) acc[i][j][q] = 0.f;

    {
        float4 a0 = *(const float4*)Ap;
        float4 a1 = *(const float4*)(Ap + (size_t)64 * lda);
        float4 b0 = *(const float4*)Bp;
        float4 b1 = *(const float4*)(Bp + (size_t)8 * ldb);
        store_tile_raw(As[0], ar,      aq, a0);
        store_tile_raw(As[0], ar + 64, aq, a1);
        *(float4*)&Bs[0][bk][bn4]     = b0;
        *(float4*)&Bs[0][bk + 8][bn4] = b1;
    }
    __syncthreads();

    const int niter = K / BK;
    int buf = 0;
    float4 pa0, pa1, pb0, pb1;

    for (int kt = 0; kt < niter; kt++) {
        const bool has_next = (kt + 1 < niter);
        if (has_next) {
            const float* An = Ap + (kt + 1) * BK;
            pa0 = *(const float4*)An;
            pa1 = *(const float4*)(An + (size_t)64 * lda);
            const float* Bn = Bp + (size_t)(kt + 1) * BK * ldb;
            pb0 = *(const float4*)Bn;
            pb1 = *(const float4*)(Bn + (size_t)8 * ldb);
        }

        const unsigned* Ab = As[buf];

        unsigned bf[4][2][2];
        #pragma unroll
        for (int nt = 0; nt < 4; nt++) {
            const int col = wn * 32 + nt * 8 + g4;
            bf[nt][0][0] = Bs[buf][c][col];
            bf[nt][0][1] = Bs[buf][c + 4][col];
            bf[nt][1][0] = Bs[buf][c + 8][col];
            bf[nt][1][1] = Bs[buf][c + 12][col];
        }

        #pragma unroll
        for (int mt = 0; mt < 4; mt++) {
            const int r = wm * 64 + mt * 16 + g4;
            uint4 lo = ld_frag_swz(Ab, r,     c);
            uint4 hi = ld_frag_swz(Ab, r + 8, c);
            unsigned af0[4] = { lo.x, hi.x, lo.y, hi.y };
            unsigned af1[4] = { lo.z, hi.z, lo.w, hi.w };
            #pragma unroll
            for (int nt = 0; nt < 4; nt++) {
                mma_tf32(acc[mt][nt], af0, bf[nt][0]);
                mma_tf32(acc[mt][nt], af1, bf[nt][1]);
            }
        }

        if (has_next) {
            unsigned* An = As[buf ^ 1];
            store_tile_raw(An, ar,      aq, pa0);
            store_tile_raw(An, ar + 64, aq, pa1);
            *(float4*)&Bs[buf ^ 1][bk][bn4]     = pb0;
            *(float4*)&Bs[buf ^ 1][bk + 8][bn4] = pb1;
        }
        __syncthreads();
        buf ^= 1;
    }

    // EPI==1: fold the 8 per-n-tile partial sums into 1/rowsum (same
    // t-order as the old inv_rows kernel -> bit-identical rinv).
    if (EPI == 1) {
        if (tid < BM) {
            float s = 0.f;
            #pragma unroll
            for (int t = 0; t < 8; t++)
                s += aux[(size_t)t * (BATCH * SEQ) + (size_t)b * SEQ + m0 + tid];
            rinv_s[tid] = 1.0f / s;
        }
        __syncthreads();
    }

    #pragma unroll
    for (int mt = 0; mt < 4; mt++) {
        const int r0 = m0 + wm * 64 + mt * 16 + g4;
        float il0 = 1.f, il1 = 1.f;
        if (EPI == 1) {
            il0 = rinv_s[wm * 64 + mt * 16 + g4];
            il1 = rinv_s[wm * 64 + mt * 16 + g4 + 8];
        }
        #pragma unroll
        for (int nt = 0; nt < 4; nt++) {
            const int col = n0 + wn * 32 + nt * 8 + 2 * c;
            float2 v0, v1;
            if (EPI == 0) {
                float bx = 0.f, by = 0.f;
                if (bias) { bx = bias[col]; by = bias[col + 1]; }
                v0 = make_float2(acc[mt][nt][0] + bx, acc[mt][nt][1] + by);
                v1 = make_float2(acc[mt][nt][2] + bx, acc[mt][nt][3] + by);
            } else {
                v0 = make_float2(acc[mt][nt][0] * il0, acc[mt][nt][1] * il0);
                v1 = make_float2(acc[mt][nt][2] * il1, acc[mt][nt][3] * il1);
            }
            if (ROUND) {
                v0.x = rnd_tf32(v0.x); v0.y = rnd_tf32(v0.y);
                v1.x = rnd_tf32(v1.x); v1.y = rnd_tf32(v1.y);
            }
            *(float2*)(C + (size_t)r0 * ldc + col) = v0;
            *(float2*)(C + (size_t)(r0 + 8) * ldc + col) = v1;
        }
    }
}

// ------------------------------------------------------------------
// NT score GEMM, fused mask + exp + partial row sums. (R9-proven)
// ------------------------------------------------------------------
__global__ void __launch_bounds__(256, 2) mma_nt_exp(
    const float* __restrict__ A, int lda, long long strideA,
    const float* __restrict__ B, int ldb, long long strideB,
    const float* __restrict__ mask,
    float scale,
    float* __restrict__ psum,
    float* __restrict__ C, int ldc, long long strideC,
    int K)
{
    __shared__ unsigned As[2][BM * BK];
    __shared__ unsigned Bs[2][BN * BK];
    __shared__ float   part[BM][8];

    const int b = blockIdx.z;
    A += (size_t)b * strideA;
    B += (size_t)b * strideB;
    C += (size_t)b * strideC;
    const float* mrow = mask + (size_t)b * SEQ;

    const int tid  = threadIdx.x;
    const int lane = tid & 31;
    const int wid  = tid >> 5;
    const int wm = wid & 3;
    const int wn = wid >> 2;
    const int m0 = blockIdx.y * BM;
    const int n0 = blockIdx.x * BN;
    const int c  = lane & 3;
    const int g4 = lane >> 2;

    const int ar = tid >> 2, aq = tid & 3;

    const float* Ap = A + (size_t)(m0 + ar) * lda + 4 * aq;
    const float* Bp = B + (size_t)(n0 + ar) * ldb + 4 * aq;

    float acc[2][8][4];
    #pragma unroll
    for (int i = 0; i < 2; i++)
        #pragma unroll
        for (int j = 0; j < 8; j++)
            #pragma unroll
            for (int q = 0; q < 4; q++) acc[i][j][q] = 0.f;

    {
        float4 a0 = *(const float4*)Ap;
        float4 a1 = *(const float4*)(Ap + (size_t)64 * lda);
        float4 b0 = *(const float4*)Bp;
        float4 b1 = *(const float4*)(Bp + (size_t)64 * ldb);
        store_tile_raw(As[0], ar,      aq, a0);
        store_tile_raw(As[0], ar + 64, aq, a1);
        store_tile_raw(Bs[0], ar,      aq, b0);
        store_tile_raw(Bs[0], ar + 64, aq, b1);
    }
    __syncthreads();

    const int niter = K / BK;
    int buf = 0;
    float4 pa0, pa1, pb0, pb1;

    for (int kt = 0; kt < niter; kt++) {
        const bool has_next = (kt + 1 < niter);
        if (has_next) {
            const float* An = Ap + (kt + 1) * BK;
            pa0 = *(const float4*)An;
            pa1 = *(const float4*)(An + (size_t)64 * lda);
            const float* Bn = Bp + (kt + 1) * BK;
            pb0 = *(const float4*)Bn;
            pb1 = *(const float4*)(Bn + (size_t)64 * ldb);
        }

        const unsigned* Ab = As[buf];
        const unsigned* Bb = Bs[buf];

        unsigned af[2][2][4];
        #pragma unroll
        for (int mt = 0; mt < 2; mt++) {
            const int r = wm * 32 + mt * 16 + g4;
            uint4 lo = ld_frag_swz(Ab, r,     c);
            uint4 hi = ld_frag_swz(Ab, r + 8, c);
            af[mt][0][0] = lo.x; af[mt][0][1] = hi.x;
            af[mt][0][2] = lo.y; af[mt][0][3] = hi.y;
            af[mt][1][0] = lo.z; af[mt][1][1] = hi.z;
            af[mt][1][2] = lo.w; af[mt][1][3] = hi.w;
        }

        #pragma unroll
        for (int nt = 0; nt < 8; nt++) {
            uint4 bv = ld_frag_swz(Bb, wn * 64 + nt * 8 + g4, c);
            unsigned b0[2] = { bv.x, bv.y };
            unsigned b1[2] = { bv.z, bv.w };
            #pragma unroll
            for (int mt = 0; mt < 2; mt++) {
                mma_tf32(acc[mt][nt], af[mt][0], b0);
                mma_tf32(acc[mt][nt], af[mt][1], b1);
            }
        }

        if (has_next) {
            unsigned* An = As[buf ^ 1];
            unsigned* Bn = Bs[buf ^ 1];
            store_tile_raw(An, ar,      aq, pa0);
            store_tile_raw(An, ar + 64, aq, pa1);
            store_tile_raw(Bn, ar,      aq, pb0);
            store_tile_raw(Bn, ar + 64, aq, pb1);
        }
        __syncthreads();
        buf ^= 1;
    }

    // Epilogue: masked exp (tf32-rounded) + write + partial row sums
    #pragma unroll
    for (int mt = 0; mt < 2; mt++) {
        const int r0 = m0 + wm * 32 + mt * 16 + g4;
        const bool rv0 = (mrow[r0] != 0.f);
        const bool rv1 = (mrow[r0 + 8] != 0.f);
        float rs0 = 0.f, rs1 = 0.f;
        #pragma unroll
        for (int nt = 0; nt < 8; nt++) {
            const int col = n0 + wn * 64 + nt * 8 + 2 * c;
            const bool cv0 = (mrow[col] != 0.f);
            const bool cv1 = (mrow[col + 1] != 0.f);
            float2 v0, v1;
            v0.x = rv0 ? (cv0 ? rnd_tf32(__expf(acc[mt][nt][0] * scale)) : 0.f) : 1.f;
            v0.y = rv0 ? (cv1 ? rnd_tf32(__expf(acc[mt][nt][1] * scale)) : 0.f) : 1.f;
            v1.x = rv1 ? (cv0 ? rnd_tf32(__expf(acc[mt][nt][2] * scale)) : 0.f) : 1.f;
            v1.y = rv1 ? (cv1 ? rnd_tf32(__expf(acc[mt][nt][3] * scale)) : 0.f) : 1.f;
            rs0 += v0.x + v0.y;
            rs1 += v1.x + v1.y;
            *(float2*)(C + (size_t)r0 * ldc + col) = v0;
            *(float2*)(C + (size_t)(r0 + 8) * ldc + col) = v1;
        }
        part[wm * 32 + mt * 16 + g4][wn * 4 + c]     = rs0;
        part[wm * 32 + mt * 16 + g4 + 8][wn * 4 + c] = rs1;
    }
    __syncthreads();
    if (tid < BM) {
        float s = 0.f;
        #pragma unroll
        for (int i = 0; i < 8; i++) s += part[tid][i];
        psum[(size_t)blockIdx.x * (BATCH * SEQ) + (size_t)b * SEQ + m0 + tid] = s;
    }
}

// ------------------------------------------------------------------
// Launch: fork/join pipeline.
//  side stream: round(txr, wkvr, wqr, wffnr) -> [ev_w] -> kv GEMM -> [ev_join]
//  main stream: round(lxr, wqkvr) -> qkv -> scores1 -> PV1(+inv) ->
//               [wait ev_w] cq -> [wait ev_join] scores2 -> PV2(+inv) -> ffn
// ------------------------------------------------------------------
extern "C" void kernel_launch(void* const* d_in, const int* in_sizes, int n_in,
                              void* d_out, int out_size)
{
    (void)in_sizes; (void)n_in; (void)out_size;

    const float* layout_x = (const float*)d_in[0];
    const float* text_x   = (const float*)d_in[1];
    const float* mask     = (const float*)d_in[2];
    const float* Wqkv     = (const float*)d_in[3];
    const float* bqkv     = (const float*)d_in[4];
    const float* Wq       = (const float*)d_in[5];
    const float* bq       = (const float*)d_in[6];
    const float* Wkv      = (const float*)d_in[7];
    const float* bkv      = (const float*)d_in[8];
    const float* Wffn     = (const float*)d_in[9];
    const float* bffn     = (const float*)d_in[10];
    float* out = (float*)d_out;

    float *qkv, *scores, *lo, *cq, *kv, *merge, *psum;
    float *lxr, *txr, *wqkvr, *wqr, *wkvr, *wffnr;
    cudaGetSymbolAddress((void**)&qkv,    g_qkv);
    cudaGetSymbolAddress((void**)&scores, g_scores);
    cudaGetSymbolAddress((void**)&lo,     g_lo);
    cudaGetSymbolAddress((void**)&cq,     g_cq);
    cudaGetSymbolAddress((void**)&kv,     g_kv);
    cudaGetSymbolAddress((void**)&merge,  g_merge);
    cudaGetSymbolAddress((void**)&psum,   g_psum);
    cudaGetSymbolAddress((void**)&lxr,    g_lxr);
    cudaGetSymbolAddress((void**)&txr,    g_txr);
    cudaGetSymbolAddress((void**)&wqkvr,  g_wqkvr);
    cudaGetSymbolAddress((void**)&wqr,    g_wqr);
    cudaGetSymbolAddress((void**)&wkvr,   g_wkvr);
    cudaGetSymbolAddress((void**)&wffnr,  g_wffnr);

    // Side stream + events (created once; host-side objects only)
    static cudaStream_t s_side = nullptr;
    static cudaEvent_t ev_fork = nullptr, ev_w = nullptr, ev_join = nullptr;
    if (s_side == nullptr) {
        cudaStreamCreateWithFlags(&s_side, cudaStreamNonBlocking);
        cudaEventCreateWithFlags(&ev_fork, cudaEventDisableTiming);
        cudaEventCreateWithFlags(&ev_w,    cudaEventDisableTiming);
        cudaEventCreateWithFlags(&ev_join, cudaEventDisableTiming);
    }

    const float scale = rsqrtf((float)CH);
    const dim3 blk(256);
    const long long sQKV = (long long)SEQ * 3 * CH;
    const long long sS   = (long long)SEQ * SEQ;
    const long long sC   = (long long)SEQ * CH;
    const long long sKV  = (long long)SEQ * 2 * CH;

    // ---- fork ----
    cudaEventRecord(ev_fork, 0);
    cudaStreamWaitEvent(s_side, ev_fork, 0);

    // side branch: all non-qkv rounds, then kv GEMM
    {
        const int nLX = BATCH * SEQ * CH / 4;
        round_tf32<<<(nLX + 255) / 256, blk, 0, s_side>>>(text_x, txr, nLX);
        const int nWkv = CH * 2 * CH / 4;
        round_tf32<<<(nWkv + 255) / 256, blk, 0, s_side>>>(Wkv, wkvr, nWkv);
        const int nWq = CH * CH / 4;
        round_tf32<<<(nWq + 255) / 256, blk, 0, s_side>>>(Wq, wqr, nWq);
        round_tf32<<<(nWq + 255) / 256, blk, 0, s_side>>>(Wffn, wffnr, nWq);
        cudaEventRecord(ev_w, s_side);   // wqr/wffnr ready
        mma_nn<0, true><<<dim3(2 * CH / BN, BATCH * SEQ / BM, 1), blk, 0, s_side>>>(
            txr, CH, 0, wkvr, 2 * CH, 0, bkv, nullptr, kv, 2 * CH, 0, CH);
    }
    cudaEventRecord(ev_join, s_side);    // kv ready

    // ---- main chain ----
    {
        const int nLX = BATCH * SEQ * CH / 4;
        round_tf32<<<(nLX + 255) / 256, blk>>>(layout_x, lxr, nLX);
        const int nWqkv = CH * 3 * CH / 4;
        round_tf32<<<(nWqkv + 255) / 256, blk>>>(Wqkv, wqkvr, nWqkv);
    }

    // 1) qkv = lxr @ Wqkv + bqkv   (rounded output)
    mma_nn<0, true><<<dim3(3 * CH / BN, BATCH * SEQ / BM, 1), blk>>>(
        lxr, CH, 0, wqkvr, 3 * CH, 0, bqkv, nullptr, qkv, 3 * CH, 0, CH);

    // 2) scores = exp(mask(Q @ K^T * scale)) + partial row sums
    mma_nt_exp<<<dim3(SEQ / BN, SEQ / BM, BATCH), blk>>>(
        qkv + 0, 3 * CH, sQKV, qkv + CH, 3 * CH, sQKV, mask, scale,
        psum, scores, SEQ, sS, CH);

    // 3) layout_o = (exp scores @ V) * (1/rowsum from psum, fused)
    mma_nn<1, true><<<dim3(CH / BN, SEQ / BM, BATCH), blk>>>(
        scores, SEQ, sS, qkv + 2 * CH, 3 * CH, sQKV, nullptr, psum,
        lo, CH, sC, SEQ);

    // 4) cq = lo @ Wq + bq   (needs wqr from the side branch)
    cudaStreamWaitEvent(0, ev_w, 0);
    mma_nn<0, true><<<dim3(CH / BN, BATCH * SEQ / BM, 1), blk>>>(
        lo, CH, 0, wqr, CH, 0, bq, nullptr, cq, CH, 0, CH);

    // ---- join: cross-attention needs kv ----
    cudaStreamWaitEvent(0, ev_join, 0);

    // 5) scores = exp(mask(CQ @ CK^T * scale)) + partial row sums
    mma_nt_exp<<<dim3(SEQ / BN, SEQ / BM, BATCH), blk>>>(
        cq, CH, sC, kv + 0, 2 * CH, sKV, mask, scale,
        psum, scores, SEQ, sS, CH);

    // 6) merge = (exp scores @ CV) * (1/rowsum, fused)
    mma_nn<1, true><<<dim3(CH / BN, SEQ / BM, BATCH), blk>>>(
        scores, SEQ, sS, kv + CH, 2 * CH, sKV, nullptr, psum,
        merge, CH, sC, SEQ);

    // 7) out = merge @ Wffn + bffn   (full f32 output)
    mma_nn<0, false><<<dim3(CH / BN, BATCH * SEQ / BM, 1), blk>>>(
        merge, CH, 0, wffnr, CH, 0, bffn, nullptr, out, CH, 0, CH);
}